// round 1
// baseline (speedup 1.0000x reference)
#include <cuda_runtime.h>
#include <cuda_bf16.h>

#define BB 64
#define SS 512
#define HH 1024
#define TT 17

// ---------------------------------------------------------------------------
// Kernel A: feats[b,s,t] = sum_h x[b,s,h] * W[t,h] + b[t]
// M = 32768 rows, K = 1024, N = 17.
// 128 threads/block, 128 rows/block, K tiled by 64 through padded smem
// (stride 68 floats => conflict-free float4 LDS). W loads are warp-uniform
// (same address across lanes) => L1 broadcast, negligible traffic.
// ---------------------------------------------------------------------------
__global__ __launch_bounds__(128) void gemm_feats(
    const float* __restrict__ x, const float* __restrict__ W,
    const float* __restrict__ bias, float* __restrict__ feats)
{
    __shared__ float xs[128][68];   // 34816 B, 68-stride => conflict-free
    const int row0 = blockIdx.x * 128;
    const int tid  = threadIdx.x;

    float acc[TT];
#pragma unroll
    for (int t = 0; t < TT; t++) acc[t] = 0.0f;

    for (int kt = 0; kt < HH / 64; kt++) {
        // Stage x tile [128 rows x 64 k] coalesced (16 threads per 256B row-chunk)
#pragma unroll
        for (int p = 0; p < 16; p++) {
            int idx = tid + p * 128;
            int r = idx >> 4;
            int c = idx & 15;
            float4 v = *(const float4*)(x + (size_t)(row0 + r) * HH + kt * 64 + c * 4);
            *(float4*)&xs[r][c * 4] = v;
        }
        __syncthreads();

        // Each thread owns one row; W broadcast via L1
#pragma unroll
        for (int c = 0; c < 16; c++) {
            float4 xv = *(const float4*)&xs[tid][c * 4];
            int k = kt * 64 + c * 4;
#pragma unroll
            for (int t = 0; t < TT; t++) {
                float4 wv = *(const float4*)(W + t * HH + k);
                acc[t] += xv.x * wv.x;
                acc[t] += xv.y * wv.y;
                acc[t] += xv.z * wv.z;
                acc[t] += xv.w * wv.w;
            }
        }
        __syncthreads();
    }

    const int row = row0 + tid;
    float* o = feats + (size_t)row * TT;
#pragma unroll
    for (int t = 0; t < TT; t++) o[t] = acc[t] + bias[t];
}

// ---------------------------------------------------------------------------
// Kernel B: Viterbi forward + backtrack. One warp per batch element.
// feats slice (34816 B) + backpointers (8704 B uint8) live in static smem.
// Lane j owns tag j; scores exchanged via warp shuffles.
// Argmax uses a >=-left tournament tree => first-occurrence semantics
// identical to jnp.argmax.
// ---------------------------------------------------------------------------
__global__ __launch_bounds__(32) void viterbi_kernel(
    const float* __restrict__ feats, const float* __restrict__ trans,
    const float* __restrict__ start_trans, const float* __restrict__ end_trans,
    const int* __restrict__ nwords, float* __restrict__ out_tags)
{
    __shared__ float fs[SS * TT];          // 34816 B
    __shared__ unsigned char bp[SS * TT];  // 8704 B

    const int b   = blockIdx.x;
    const int tid = threadIdx.x;

    // Load this batch's feats into smem (2176 float4, coalesced)
    const float4* fb4 = (const float4*)(feats + (size_t)b * SS * TT);
    for (int i = tid; i < (SS * TT) / 4; i += 32)
        ((float4*)fs)[i] = fb4[i];

    const int jj = (tid < TT) ? tid : (TT - 1);  // lanes >= 17 shadow lane 16
    float tcol[TT];                              // trans[i][jj], column for my tag
#pragma unroll
    for (int i = 0; i < TT; i++) tcol[i] = trans[i * TT + jj];
    const int nw = nwords[b];
    __syncthreads();

    float score = start_trans[jj] + fs[jj];      // t = 0 init (mask[0] always true)

    for (int t = 1; t < SS; t++) {
        float c[TT];
#pragma unroll
        for (int i = 0; i < TT; i++) {
            float si = __shfl_sync(0xffffffffu, score, i);
            c[i] = si + tcol[i];
        }
        // first-max tournament over 17 candidates
        float w8[8]; int j8[8];
#pragma unroll
        for (int p = 0; p < 8; p++) {
            bool g = c[2 * p] >= c[2 * p + 1];
            w8[p] = g ? c[2 * p] : c[2 * p + 1];
            j8[p] = g ? 2 * p : 2 * p + 1;
        }
        float w4[4]; int j4[4];
#pragma unroll
        for (int p = 0; p < 4; p++) {
            bool g = w8[2 * p] >= w8[2 * p + 1];
            w4[p] = g ? w8[2 * p] : w8[2 * p + 1];
            j4[p] = g ? j8[2 * p] : j8[2 * p + 1];
        }
        float w2[2]; int j2[2];
#pragma unroll
        for (int p = 0; p < 2; p++) {
            bool g = w4[2 * p] >= w4[2 * p + 1];
            w2[p] = g ? w4[2 * p] : w4[2 * p + 1];
            j2[p] = g ? j4[2 * p] : j4[2 * p + 1];
        }
        bool g1 = w2[0] >= w2[1];
        float bv = g1 ? w2[0] : w2[1];
        int   bi = g1 ? j2[0] : j2[1];
        bool g0 = bv >= c[16];
        bi = g0 ? bi : 16;
        bv = g0 ? bv : c[16];

        const bool m = (t < nw);
        const float f = fs[t * TT + jj];
        score = m ? (bv + f) : score;
        int bpv = m ? bi : jj;
        if (tid < TT) bp[t * TT + jj] = (unsigned char)bpv;
    }

    // final = score + end_trans ; last_tag = first-argmax
    float fin[TT];
#pragma unroll
    for (int i = 0; i < TT; i++)
        fin[i] = __shfl_sync(0xffffffffu, score, i) + end_trans[i];

    __syncthreads();  // make bp stores visible to lane 0

    if (tid == 0) {
        int cur = 0;
        float bv = fin[0];
#pragma unroll
        for (int i = 1; i < TT; i++) {
            if (fin[i] > bv) { bv = fin[i]; cur = i; }
        }
        float* o = out_tags + (size_t)b * SS;
        for (int t = SS - 1; t >= 1; t--) {
            o[t] = (t < nw) ? (float)cur : 0.0f;
            cur = bp[t * TT + cur];
        }
        o[0] = (float)cur;  // mask[0] always true (nwords >= 1)
    }
}

// ---------------------------------------------------------------------------
// Inputs (metadata order): x, W, b, transitions, start_trans, end_trans, nwords
// Output: [padded_tags (B*S) | feats (B*S*T)] as float32
// ---------------------------------------------------------------------------
extern "C" void kernel_launch(void* const* d_in, const int* in_sizes, int n_in,
                              void* d_out, int out_size)
{
    const float* x     = (const float*)d_in[0];
    const float* W     = (const float*)d_in[1];
    const float* bias  = (const float*)d_in[2];
    const float* trans = (const float*)d_in[3];
    const float* st    = (const float*)d_in[4];
    const float* en    = (const float*)d_in[5];
    const int*   nw    = (const int*)d_in[6];

    float* out   = (float*)d_out;
    float* tags  = out;                // B*S
    float* feats = out + BB * SS;      // B*S*T

    gemm_feats<<<(BB * SS) / 128, 128>>>(x, W, bias, feats);
    viterbi_kernel<<<BB, 32>>>(feats, trans, st, en, nw, tags);
}

// round 7
// speedup vs baseline: 1.3775x; 1.3775x over previous
#include <cuda_runtime.h>
#include <cuda_bf16.h>

#define BB 64
#define SS 512
#define HH 1024
#define TT 17

// ---------------------------------------------------------------------------
// GEMM: feats[r][t] = sum_h x[r][h]*W[t][h] + b[t], r = 0..32767 (M=32768,
// K=1024, N=17). 128 threads / 128 rows per block. Per k-tile (64), both the
// x tile and a W slab [17 x 64] are staged in STATIC smem (39.4 KB total, no
// opt-in needed, ~5 CTAs/SM). W reads in the inner loop are warp-uniform =>
// LDS broadcast. Accumulation uses packed fma.rn.f32x2 (FFMA2): even/odd-k
// partial sums in one b64 register => half the FMA issue count.
// ---------------------------------------------------------------------------
#define GEMM_THREADS 128
#define ROWS_PB      128
#define KTILE        64
#define XS_STRIDE    68      // floats; 272 B row stride, 16B-aligned, conflict-free
#define WT_STRIDE    68

typedef unsigned long long u64;

__device__ __forceinline__ u64 fma2(u64 a, u64 b, u64 c) {
    u64 d;
    asm("fma.rn.f32x2 %0, %1, %2, %3;" : "=l"(d) : "l"(a), "l"(b), "l"(c));
    return d;
}

__global__ __launch_bounds__(GEMM_THREADS) void gemm_feats(
    const float* __restrict__ x, const float* __restrict__ W,
    const float* __restrict__ bias, float* __restrict__ feats)
{
    __shared__ float xs[ROWS_PB * XS_STRIDE];   // 34816 B
    __shared__ float wt[TT * WT_STRIDE];        //  4624 B

    const int tid  = threadIdx.x;
    const int row0 = blockIdx.x * ROWS_PB;

    u64 acc[TT];
#pragma unroll
    for (int t = 0; t < TT; t++) acc[t] = 0ull;

    for (int kt = 0; kt < HH / KTILE; kt++) {
        // Stage x tile [128 rows x 64 k], coalesced (16 threads per row-chunk)
#pragma unroll
        for (int p = 0; p < 16; p++) {
            int idx = tid + p * GEMM_THREADS;
            int r = idx >> 4;
            int c = idx & 15;
            float4 v = *(const float4*)(x + (size_t)(row0 + r) * HH + kt * KTILE + c * 4);
            *(float4*)&xs[r * XS_STRIDE + c * 4] = v;
        }
        // Stage W slab [17 tags x 64 k] (272 float4)
        for (int idx = tid; idx < TT * 16; idx += GEMM_THREADS) {
            int t = idx >> 4;
            int c = idx & 15;
            float4 v = *(const float4*)(W + (size_t)t * HH + kt * KTILE + c * 4);
            *(float4*)&wt[t * WT_STRIDE + c * 4] = v;
        }
        __syncthreads();

#pragma unroll
        for (int c = 0; c < 16; c++) {
            ulonglong2 xv = *(const ulonglong2*)&xs[tid * XS_STRIDE + c * 4];
#pragma unroll
            for (int t = 0; t < TT; t++) {
                ulonglong2 wv = *(const ulonglong2*)&wt[t * WT_STRIDE + c * 4];
                acc[t] = fma2(xv.x, wv.x, acc[t]);
                acc[t] = fma2(xv.y, wv.y, acc[t]);
            }
        }
        __syncthreads();
    }

    float* o = feats + (size_t)(row0 + tid) * TT;
#pragma unroll
    for (int t = 0; t < TT; t++) {
        float2 p = *(float2*)&acc[t];
        o[t] = p.x + p.y + bias[t];
    }
}

// ---------------------------------------------------------------------------
// Viterbi: one block (128 threads) per batch element. All 4 warps cooperate
// on the feats smem fill; warp 0 alone runs the sequential scan (lane j owns
// tag j) and the backtrack. Argmax = FMNMX value tree (4 cyc/level) +
// parallel equality + IMNMX index min-tree (first-occurrence semantics ==
// jnp.argmax). Forward loop breaks at t >= nw: beyond it the reference
// keeps score frozen and bp = identity, and those tags are masked to 0.
// ---------------------------------------------------------------------------
__global__ __launch_bounds__(128) void viterbi_kernel(
    const float* __restrict__ feats, const float* __restrict__ trans,
    const float* __restrict__ start_trans, const float* __restrict__ end_trans,
    const int* __restrict__ nwords, float* __restrict__ out_tags)
{
    __shared__ float fs[SS * TT];          // 34816 B
    __shared__ unsigned char bp[SS * TT];  //  8704 B

    const int b   = blockIdx.x;
    const int tid = threadIdx.x;

    // Cooperative feats fill: 2176 float4 over 128 threads (17 iters)
    const float4* fb4 = (const float4*)(feats + (size_t)b * SS * TT);
    for (int i = tid; i < (SS * TT) / 4; i += 128)
        ((float4*)fs)[i] = fb4[i];
    __syncthreads();

    if (tid >= 32) return;   // warps 1-3 done (exited threads satisfy barriers)

    const int jj = (tid < TT) ? tid : (TT - 1);   // lanes >= 17 shadow tag 16
    float tcol[TT];
#pragma unroll
    for (int i = 0; i < TT; i++) tcol[i] = trans[i * TT + jj];
    const int nw = nwords[b];

    float score = start_trans[jj] + fs[jj];       // t = 0 (always unmasked)

    for (int t = 1; t < nw; t++) {
        const float f = fs[t * TT + jj];          // independent LDS, prefetched

        float c[TT];
#pragma unroll
        for (int i = 0; i < TT; i++) {
            float si = __shfl_sync(0xffffffffu, score, i);
            c[i] = si + tcol[i];
        }

        // max value: FMNMX tree, depth 5
        float m8[8];
#pragma unroll
        for (int p = 0; p < 8; p++) m8[p] = fmaxf(c[2 * p], c[2 * p + 1]);
        float m4[4];
#pragma unroll
        for (int p = 0; p < 4; p++) m4[p] = fmaxf(m8[2 * p], m8[2 * p + 1]);
        float bv = fmaxf(fmaxf(fmaxf(m4[0], m4[1]), fmaxf(m4[2], m4[3])), c[16]);

        // first index equal to bv: parallel equality + IMNMX min-tree
        int e[TT];
#pragma unroll
        for (int i = 0; i < TT; i++) e[i] = (c[i] == bv) ? i : 31;
        int i8[8];
#pragma unroll
        for (int p = 0; p < 8; p++) i8[p] = min(e[2 * p], e[2 * p + 1]);
        int i4[4];
#pragma unroll
        for (int p = 0; p < 4; p++) i4[p] = min(i8[2 * p], i8[2 * p + 1]);
        int bi = min(min(min(i4[0], i4[1]), min(i4[2], i4[3])), e[16]);

        score = bv + f;
        if (tid < TT) bp[t * TT + jj] = (unsigned char)bi;
    }

    float fin[TT];
#pragma unroll
    for (int i = 0; i < TT; i++)
        fin[i] = __shfl_sync(0xffffffffu, score, i) + end_trans[i];

    __syncwarp();   // bp stores (warp 0 only) visible to lane 0

    if (tid == 0) {
        int cur = 0;
        float bv = fin[0];
#pragma unroll
        for (int i = 1; i < TT; i++)
            if (fin[i] > bv) { bv = fin[i]; cur = i; }

        float* o = out_tags + (size_t)b * SS;
        int t = SS - 1;
        for (; t >= nw; t--) o[t] = 0.0f;          // masked region (bp identity)
        for (; t >= 1; t--) {
            o[t] = (float)cur;
            cur = bp[t * TT + cur];
        }
        o[0] = (float)cur;                          // nwords >= 1
    }
}

// ---------------------------------------------------------------------------
// Inputs: x, W, b, transitions, start_trans, end_trans, nwords
// Output: [padded_tags (B*S) | feats (B*S*T)] float32
// ---------------------------------------------------------------------------
extern "C" void kernel_launch(void* const* d_in, const int* in_sizes, int n_in,
                              void* d_out, int out_size)
{
    const float* x     = (const float*)d_in[0];
    const float* W     = (const float*)d_in[1];
    const float* bias  = (const float*)d_in[2];
    const float* trans = (const float*)d_in[3];
    const float* st    = (const float*)d_in[4];
    const float* en    = (const float*)d_in[5];
    const int*   nw    = (const int*)d_in[6];

    float* out   = (float*)d_out;
    float* tags  = out;                // B*S
    float* feats = out + BB * SS;      // B*S*T

    gemm_feats<<<(BB * SS) / ROWS_PB, GEMM_THREADS>>>(x, W, bias, feats);
    viterbi_kernel<<<BB, 128>>>(feats, trans, st, en, nw, tags);
}